// round 9
// baseline (speedup 1.0000x reference)
#include <cuda_runtime.h>

// Single fused ball-query kernel, direct-binned 12^3 grid, 2 grid barriers.
// N1=4096 queries, N2=16384 refs, K=32, r=0.08, points uniform [0,1)^3.
//
// R9 vs R8: occupancy geometry. 512 blocks x 256 threads with
// launch_bounds(256,5): reg cap ~51 with 5 co-resident blocks -> up to 40
// warps/SM (vs 24-32 at the old 64-reg/2-block config). More eligible warps
// per SMSP overlap the L2-latency stalls that capped issue at 33%.
// Build = 32 pts/block (all 512 blocks), zero = 4 cells/block.
// Query algorithm unchanged from R8 (27-counter wave, 3x3 batched rows).
//
// Replay-safe: g_n zeroed in phase 0 each call; barrier counters monotone.
// Deterministic: hits ranked by unique original index.
//
// Hit predicate bit-identical to verified formula (rel_err 0.0 x8):
//   s = ((x*x + y*y) + z*z)  (mul/add, no fma contraction)
//   dot = fmaf(z1,z2, fmaf(y1,y2, x1*x2))
//   d2  = (s1 + s2) - 2*dot;  hit iff d2 <= r^2

#define BQ_N1 4096
#define BQ_N2 16384
#define BQ_K 32
#define BQ_R2 0.0064f
#define BQ_R2P 0.00641f
#define BQ_G 12
#define BQ_NC (BQ_G * BQ_G * BQ_G)  // 1728
#define BQ_CAP 48
#define BQ_BUF 128
#define NBLK 512
#define NTHR 256
#define NWARP 8
#define ZPB 4                       // 512*4 = 2048 >= 1728
#define PPB 32                      // 512*32 = 16384

__device__ unsigned g_arrive;           // monotone arrival tickets
__device__ unsigned g_release;          // monotone release generations
__device__ int g_n[BQ_NC];
__device__ float4 g_cp[BQ_NC * BQ_CAP]; // x, y, z, idx_bits

__device__ __forceinline__ int cell1(float v) {
    int c = (int)(v * (float)BQ_G);
    return c < 0 ? 0 : (c > BQ_G - 1 ? BQ_G - 1 : c);
}

// Grid barrier: release fence, thread-0 ticket, spin on read-only release
// word. 512 blocks co-resident (launch_bounds(256,5): 5*148 = 740 >= 512)
// -> deadlock-free.
__device__ __forceinline__ void gbar() {
    __syncthreads();
    __threadfence();
    if (threadIdx.x == 0) {
        unsigned my = atomicAdd(&g_arrive, 1u);
        unsigned target = my / NBLK + 1u;
        if (my % NBLK == NBLK - 1u)
            atomicAdd(&g_release, 1u);
        else
            while (*(volatile unsigned*)&g_release < target) __nanosleep(20);
    }
    __syncthreads();
}

__global__ __launch_bounds__(NTHR, 5) void bq_all(const float* __restrict__ p1,
                                                  const float* __restrict__ p2,
                                                  float* __restrict__ out) {
    __shared__ int sh_key[NWARP][BQ_BUF];  // 4 KB packed hit records
    __shared__ int s_wcnt[NWARP];

    int tid = threadIdx.x;
    int warp = tid >> 5;
    int lane = tid & 31;
    int q = blockIdx.x * NWARP + warp;     // 512*8 = 4096 queries

    // ---- Phase 0: zero counters, init, query-point setup ----
    if (tid < ZPB) {
        int c = blockIdx.x * ZPB + tid;
        if (c < BQ_NC) g_n[c] = 0;
    }
    if (tid < NWARP) s_wcnt[tid] = 0;

    float x1 = p1[3 * q + 0];
    float y1 = p1[3 * q + 1];
    float z1 = p1[3 * q + 2];
    float s1 = __fadd_rn(__fadd_rn(__fmul_rn(x1, x1), __fmul_rn(y1, y1)),
                         __fmul_rn(z1, z1));
    int cx = cell1(x1), cy = cell1(y1), cz = cell1(z1);
    int xlo = cx > 0 ? cx - 1 : 0;
    int xhi = cx < BQ_G - 1 ? cx + 1 : BQ_G - 1;
    const float invG = 1.0f / (float)BQ_G;
    float dxl = x1 - (float)cx * invG, dxr = (float)(cx + 1) * invG - x1;
    float dyl = y1 - (float)cy * invG, dyr = (float)(cy + 1) * invG - y1;
    float dzl = z1 - (float)cz * invG, dzr = (float)(cz + 1) * invG - z1;
    float dxl2 = dxl * dxl, dxr2 = dxr * dxr;
    gbar();

    // ---- Phase 1: build, 32 points/block (all SMs busy) ----
    if (tid < PPB) {
        int j = blockIdx.x * PPB + tid;
        float px = p2[3 * j + 0];
        float py = p2[3 * j + 1];
        float pz = p2[3 * j + 2];
        int c = (cell1(pz) * BQ_G + cell1(py)) * BQ_G + cell1(px);
        int slot = atomicAdd(&g_n[c], 1);
        if (slot < BQ_CAP)
            g_cp[c * BQ_CAP + slot] =
                make_float4(px, py, pz, __int_as_float(j));
    }
    gbar();

    // ---- Phase 2: query ----
    int* keyb = sh_key[warp];
    int* wcnt = &s_wcnt[warp];

    // Row descriptors: all 27 counter loads issue as one independent wave.
    int rbase[9], rpack[9];  // rpack = n0 | n01<<8 | tot<<16
    #pragma unroll
    for (int r = 0; r < 9; r++) {
        int dzi = r / 3 - 1, dyi = r % 3 - 1;
        int zz = cz + dzi, yy = cy + dyi;
        float ddz = (dzi < 0) ? dzl : ((dzi > 0) ? dzr : 0.0f);
        float ddy = (dyi < 0) ? dyl : ((dyi > 0) ? dyr : 0.0f);
        float dyz2 = ddz * ddz + ddy * ddy;
        bool ok = (zz >= 0) && (zz < BQ_G) && (yy >= 0) && (yy < BQ_G) &&
                  (dyz2 <= BQ_R2P);
        int xl = xlo, xh = xhi;
        if (xl < cx && dxl2 + dyz2 > BQ_R2P) xl = cx;
        if (xh > cx && dxr2 + dyz2 > BQ_R2P) xh = cx;
        int c0 = (zz * BQ_G + yy) * BQ_G + xl;
        int nc = xh - xl + 1;
        int n0 = 0, n1 = 0, n2 = 0;
        if (ok) {
            n0 = min(g_n[c0], BQ_CAP);
            if (nc > 1) n1 = min(g_n[c0 + 1], BQ_CAP);
            if (nc > 2) n2 = min(g_n[c0 + 2], BQ_CAP);
        }
        rbase[r] = c0 * BQ_CAP;
        rpack[r] = n0 | ((n0 + n1) << 8) | ((n0 + n1 + n2) << 16);
    }

    // Rows in 3 groups of 3: each group's candidate loads issue back-to-back
    // before any test consumes them (3 L2 waves, not 9).
    #pragma unroll
    for (int grp = 0; grp < 3; grp++) {
        float4 pb[3];
        int ta[3], tt[3];
        #pragma unroll
        for (int k = 0; k < 3; k++) {
            int r = grp * 3 + k;
            int n0 = rpack[r] & 0xff;
            int n01 = (rpack[r] >> 8) & 0xff;
            int tot = rpack[r] >> 16;
            tt[k] = tot;
            int t = lane;
            int a = rbase[r] + (t < n0 ? t
                    : (t < n01 ? BQ_CAP + t - n0 : 2 * BQ_CAP + t - n01));
            ta[k] = a;
            if (t < tot) pb[k] = g_cp[a];
        }
        #pragma unroll
        for (int k = 0; k < 3; k++) {
            if (lane < tt[k]) {
                float4 p = pb[k];
                float s2 = __fadd_rn(
                    __fadd_rn(__fmul_rn(p.x, p.x), __fmul_rn(p.y, p.y)),
                    __fmul_rn(p.z, p.z));
                float dot = fmaf(z1, p.z, fmaf(y1, p.y, __fmul_rn(x1, p.x)));
                float d2 = __fsub_rn(__fadd_rn(s1, s2), __fmul_rn(2.0f, dot));
                if (d2 <= BQ_R2) {
                    int pos = atomicAdd(wcnt, 1);
                    if (pos < BQ_BUF)
                        keyb[pos] = (__float_as_int(p.w) << 17) | ta[k];
                }
            }
        }
        // Overflow pass: rows with tot > 32 (uncommon).
        #pragma unroll
        for (int k = 0; k < 3; k++) {
            int r = grp * 3 + k;
            int n0 = rpack[r] & 0xff;
            int n01 = (rpack[r] >> 8) & 0xff;
            for (int t = 32 + lane; t < tt[k]; t += 32) {
                int a = rbase[r] + (t < n0 ? t
                        : (t < n01 ? BQ_CAP + t - n0 : 2 * BQ_CAP + t - n01));
                float4 p = g_cp[a];
                float s2 = __fadd_rn(
                    __fadd_rn(__fmul_rn(p.x, p.x), __fmul_rn(p.y, p.y)),
                    __fmul_rn(p.z, p.z));
                float dot = fmaf(z1, p.z, fmaf(y1, p.y, __fmul_rn(x1, p.x)));
                float d2 = __fsub_rn(__fadd_rn(s1, s2), __fmul_rn(2.0f, dot));
                if (d2 <= BQ_R2) {
                    int pos = atomicAdd(wcnt, 1);
                    if (pos < BQ_BUF)
                        keyb[pos] = (__float_as_int(p.w) << 17) | a;
                }
            }
        }
    }
    __syncwarp();
    int cnt = *wcnt;
    __syncwarp();

    float* mapping = out + (size_t)q * BQ_K;
    float* num_out = out + (size_t)BQ_N1 * BQ_K + q;
    float* coords  = out + (size_t)BQ_N1 * BQ_K + BQ_N1 + (size_t)q * BQ_K * 3;

    int cc = cnt < BQ_BUF ? cnt : BQ_BUF;
    // Rank by packed key (idx-major, idx unique) -> reference's "first K in
    // ascending original index" order, independent of append order.
    for (int e0 = lane; e0 < cc; e0 += 32) {
        int key = keyb[e0];
        int rank = 0;
        for (int i = 0; i < cc; i++) rank += (keyb[i] < key);
        if (rank < BQ_K) {
            float4 p = g_cp[key & 0x1FFFF];  // L1-hot reload
            mapping[rank] = (float)(key >> 17);
            coords[rank * 3 + 0] = p.x;
            coords[rank * 3 + 1] = p.y;
            coords[rank * 3 + 2] = p.z;
        }
    }

    int n = cnt < BQ_K ? cnt : BQ_K;
    if (lane == 0) *num_out = (float)n;
    for (int s = n + lane; s < BQ_K; s += 32) {
        mapping[s] = 0.0f;
        coords[s * 3 + 0] = 0.0f;
        coords[s * 3 + 1] = 0.0f;
        coords[s * 3 + 2] = 0.0f;
    }
}

extern "C" void kernel_launch(void* const* d_in, const int* in_sizes, int n_in,
                              void* d_out, int out_size) {
    const float* p1 = (const float*)d_in[0];
    const float* p2 = (const float*)d_in[1];
    float* out = (float*)d_out;
    bq_all<<<NBLK, NTHR>>>(p1, p2, out);
}

// round 10
// speedup vs baseline: 1.0288x; 1.0288x over previous
#include <cuda_runtime.h>

// Single fused ball-query kernel, direct-binned 12^3 grid, 2 grid barriers.
// N1=4096 queries, N2=16384 refs, K=32, r=0.08, points uniform [0,1)^3.
//
// R10 = R8 (measured-best config: 256 blocks x 512 threads) with the grid
// barrier rebuilt fence-free: __syncthreads + thread-0 acq_rel ticket atomic
// + acquire-load poll, instead of per-thread __threadfence (16 warps x
// MEMBAR.GPU x 2 barriers of MIO-serialized fence cost removed).
// Memory-model: syncthreads orders block writes before t0's release arrival;
// waiter's acquire poll + syncthreads gives block-wide acquire (the
// cooperative-groups grid.sync pattern). Post-barrier plain loads are safe:
// g_n/g_cp are store-only before their consuming barrier (stores don't
// allocate L1), as R8's rel_err 0.0 already demonstrated.
//
// Replay-safe: g_n zeroed in phase 0 each call; barrier counters monotone.
// Deterministic: hits ranked by unique original index.
//
// Hit predicate bit-identical to verified formula (rel_err 0.0 x9):
//   s = ((x*x + y*y) + z*z)  (mul/add, no fma contraction)
//   dot = fmaf(z1,z2, fmaf(y1,y2, x1*x2))
//   d2  = (s1 + s2) - 2*dot;  hit iff d2 <= r^2

#define BQ_N1 4096
#define BQ_N2 16384
#define BQ_K 32
#define BQ_R2 0.0064f
#define BQ_R2P 0.00641f
#define BQ_G 12
#define BQ_NC (BQ_G * BQ_G * BQ_G)  // 1728
#define BQ_CAP 48
#define BQ_BUF 128
#define NBLK 256
#define NTHR 512
#define NWARP 16
#define ZPB 7                       // 256*7 = 1792 >= 1728
#define PPB 64                      // 256*64 = 16384

__device__ unsigned g_arrive;           // monotone arrival tickets
__device__ unsigned g_release;          // monotone release generations
__device__ int g_n[BQ_NC];
__device__ float4 g_cp[BQ_NC * BQ_CAP]; // x, y, z, idx_bits

__device__ __forceinline__ int cell1(float v) {
    int c = (int)(v * (float)BQ_G);
    return c < 0 ? 0 : (c > BQ_G - 1 ? BQ_G - 1 : c);
}

// Fence-free grid barrier (ticket / release-word split, acq_rel semantics).
// 256 blocks co-resident (launch_bounds(512,2): 296 >= 256) -> deadlock-free.
__device__ __forceinline__ void gbar() {
    __syncthreads();
    if (threadIdx.x == 0) {
        unsigned my;
        asm volatile("atom.add.acq_rel.gpu.global.u32 %0, [%1], %2;"
                     : "=r"(my) : "l"(&g_arrive), "r"(1u) : "memory");
        unsigned target = my / NBLK + 1u;
        if (my % NBLK == NBLK - 1u) {
            asm volatile("red.add.release.gpu.global.u32 [%0], %1;"
                         :: "l"(&g_release), "r"(1u) : "memory");
        } else {
            unsigned v;
            do {
                __nanosleep(20);
                asm volatile("ld.acquire.gpu.global.u32 %0, [%1];"
                             : "=r"(v) : "l"(&g_release) : "memory");
            } while (v < target);
        }
    }
    __syncthreads();
}

__global__ __launch_bounds__(NTHR, 2) void bq_all(const float* __restrict__ p1,
                                                  const float* __restrict__ p2,
                                                  float* __restrict__ out) {
    __shared__ int sh_key[NWARP][BQ_BUF];  // 8 KB packed hit records
    __shared__ int s_wcnt[NWARP];

    int tid = threadIdx.x;
    int warp = tid >> 5;
    int lane = tid & 31;
    int q = blockIdx.x * NWARP + warp;     // 4096 queries, one per warp

    // ---- Phase 0: zero counters, init, query-point setup ----
    if (tid < ZPB) {
        int c = blockIdx.x * ZPB + tid;
        if (c < BQ_NC) g_n[c] = 0;
    }
    if (tid < NWARP) s_wcnt[tid] = 0;

    float x1 = p1[3 * q + 0];
    float y1 = p1[3 * q + 1];
    float z1 = p1[3 * q + 2];
    float s1 = __fadd_rn(__fadd_rn(__fmul_rn(x1, x1), __fmul_rn(y1, y1)),
                         __fmul_rn(z1, z1));
    int cx = cell1(x1), cy = cell1(y1), cz = cell1(z1);
    int xlo = cx > 0 ? cx - 1 : 0;
    int xhi = cx < BQ_G - 1 ? cx + 1 : BQ_G - 1;
    const float invG = 1.0f / (float)BQ_G;
    float dxl = x1 - (float)cx * invG, dxr = (float)(cx + 1) * invG - x1;
    float dyl = y1 - (float)cy * invG, dyr = (float)(cy + 1) * invG - y1;
    float dzl = z1 - (float)cz * invG, dzr = (float)(cz + 1) * invG - z1;
    float dxl2 = dxl * dxl, dxr2 = dxr * dxr;
    gbar();

    // ---- Phase 1: build, 64 points/block (all SMs busy) ----
    if (tid < PPB) {
        int j = blockIdx.x * PPB + tid;
        float px = p2[3 * j + 0];
        float py = p2[3 * j + 1];
        float pz = p2[3 * j + 2];
        int c = (cell1(pz) * BQ_G + cell1(py)) * BQ_G + cell1(px);
        int slot = atomicAdd(&g_n[c], 1);
        if (slot < BQ_CAP)
            g_cp[c * BQ_CAP + slot] =
                make_float4(px, py, pz, __int_as_float(j));
    }
    gbar();

    // ---- Phase 2: query ----
    int* keyb = sh_key[warp];
    int* wcnt = &s_wcnt[warp];

    // Row descriptors: all 27 counter loads issue as one independent wave.
    int rbase[9], rpack[9];  // rpack = n0 | n01<<8 | tot<<16
    #pragma unroll
    for (int r = 0; r < 9; r++) {
        int dzi = r / 3 - 1, dyi = r % 3 - 1;
        int zz = cz + dzi, yy = cy + dyi;
        float ddz = (dzi < 0) ? dzl : ((dzi > 0) ? dzr : 0.0f);
        float ddy = (dyi < 0) ? dyl : ((dyi > 0) ? dyr : 0.0f);
        float dyz2 = ddz * ddz + ddy * ddy;
        bool ok = (zz >= 0) && (zz < BQ_G) && (yy >= 0) && (yy < BQ_G) &&
                  (dyz2 <= BQ_R2P);
        int xl = xlo, xh = xhi;
        if (xl < cx && dxl2 + dyz2 > BQ_R2P) xl = cx;
        if (xh > cx && dxr2 + dyz2 > BQ_R2P) xh = cx;
        int c0 = (zz * BQ_G + yy) * BQ_G + xl;
        int nc = xh - xl + 1;
        int n0 = 0, n1 = 0, n2 = 0;
        if (ok) {
            n0 = min(g_n[c0], BQ_CAP);
            if (nc > 1) n1 = min(g_n[c0 + 1], BQ_CAP);
            if (nc > 2) n2 = min(g_n[c0 + 2], BQ_CAP);
        }
        rbase[r] = c0 * BQ_CAP;
        rpack[r] = n0 | ((n0 + n1) << 8) | ((n0 + n1 + n2) << 16);
    }

    // Rows in 3 groups of 3: each group's candidate loads issue back-to-back
    // before any test consumes them (3 L2 waves, not 9).
    #pragma unroll
    for (int grp = 0; grp < 3; grp++) {
        float4 pb[3];
        int ta[3], tt[3];
        #pragma unroll
        for (int k = 0; k < 3; k++) {
            int r = grp * 3 + k;
            int n0 = rpack[r] & 0xff;
            int n01 = (rpack[r] >> 8) & 0xff;
            int tot = rpack[r] >> 16;
            tt[k] = tot;
            int t = lane;
            int a = rbase[r] + (t < n0 ? t
                    : (t < n01 ? BQ_CAP + t - n0 : 2 * BQ_CAP + t - n01));
            ta[k] = a;
            if (t < tot) pb[k] = g_cp[a];
        }
        #pragma unroll
        for (int k = 0; k < 3; k++) {
            if (lane < tt[k]) {
                float4 p = pb[k];
                float s2 = __fadd_rn(
                    __fadd_rn(__fmul_rn(p.x, p.x), __fmul_rn(p.y, p.y)),
                    __fmul_rn(p.z, p.z));
                float dot = fmaf(z1, p.z, fmaf(y1, p.y, __fmul_rn(x1, p.x)));
                float d2 = __fsub_rn(__fadd_rn(s1, s2), __fmul_rn(2.0f, dot));
                if (d2 <= BQ_R2) {
                    int pos = atomicAdd(wcnt, 1);
                    if (pos < BQ_BUF)
                        keyb[pos] = (__float_as_int(p.w) << 17) | ta[k];
                }
            }
        }
        // Overflow pass: rows with tot > 32 (uncommon).
        #pragma unroll
        for (int k = 0; k < 3; k++) {
            int r = grp * 3 + k;
            int n0 = rpack[r] & 0xff;
            int n01 = (rpack[r] >> 8) & 0xff;
            for (int t = 32 + lane; t < tt[k]; t += 32) {
                int a = rbase[r] + (t < n0 ? t
                        : (t < n01 ? BQ_CAP + t - n0 : 2 * BQ_CAP + t - n01));
                float4 p = g_cp[a];
                float s2 = __fadd_rn(
                    __fadd_rn(__fmul_rn(p.x, p.x), __fmul_rn(p.y, p.y)),
                    __fmul_rn(p.z, p.z));
                float dot = fmaf(z1, p.z, fmaf(y1, p.y, __fmul_rn(x1, p.x)));
                float d2 = __fsub_rn(__fadd_rn(s1, s2), __fmul_rn(2.0f, dot));
                if (d2 <= BQ_R2) {
                    int pos = atomicAdd(wcnt, 1);
                    if (pos < BQ_BUF)
                        keyb[pos] = (__float_as_int(p.w) << 17) | a;
                }
            }
        }
    }
    __syncwarp();
    int cnt = *wcnt;
    __syncwarp();

    float* mapping = out + (size_t)q * BQ_K;
    float* num_out = out + (size_t)BQ_N1 * BQ_K + q;
    float* coords  = out + (size_t)BQ_N1 * BQ_K + BQ_N1 + (size_t)q * BQ_K * 3;

    int cc = cnt < BQ_BUF ? cnt : BQ_BUF;
    // Rank by packed key (idx-major, idx unique) -> reference's "first K in
    // ascending original index" order, independent of append order.
    for (int e0 = lane; e0 < cc; e0 += 32) {
        int key = keyb[e0];
        int rank = 0;
        for (int i = 0; i < cc; i++) rank += (keyb[i] < key);
        if (rank < BQ_K) {
            float4 p = g_cp[key & 0x1FFFF];  // L1-hot reload
            mapping[rank] = (float)(key >> 17);
            coords[rank * 3 + 0] = p.x;
            coords[rank * 3 + 1] = p.y;
            coords[rank * 3 + 2] = p.z;
        }
    }

    int n = cnt < BQ_K ? cnt : BQ_K;
    if (lane == 0) *num_out = (float)n;
    for (int s = n + lane; s < BQ_K; s += 32) {
        mapping[s] = 0.0f;
        coords[s * 3 + 0] = 0.0f;
        coords[s * 3 + 1] = 0.0f;
        coords[s * 3 + 2] = 0.0f;
    }
}

extern "C" void kernel_launch(void* const* d_in, const int* in_sizes, int n_in,
                              void* d_out, int out_size) {
    const float* p1 = (const float*)d_in[0];
    const float* p2 = (const float*)d_in[1];
    float* out = (float*)d_out;
    bq_all<<<NBLK, NTHR>>>(p1, p2, out);
}

// round 11
// speedup vs baseline: 1.1335x; 1.1017x over previous
#include <cuda_runtime.h>

// Single fused ball-query kernel, direct-binned 12^3 grid, ONE grid barrier.
// N1=4096 queries, N2=16384 refs, K=32, r=0.08, points uniform [0,1)^3.
//
// R11 vs R10:
//  - Generation-parity double-buffered cell counters: entry ticket gives all
//    blocks the call index (calls are serialized, so tickets [call*NBLK,
//    (call+1)*NBLK) -> same call/NBLK for every block). Build/query use
//    g_n[call&1]; each block zeroes g_n[1-(call&1)] for the NEXT call
//    (no concurrent reader; first call covered by .bss zeros).
//    -> the zero->build barrier is gone; one barrier remains (build->query).
//  - Coalesced staged epilogue: outputs assembled in a 128-float shared
//    buffer per warp, then 4 coalesced STG.32 per lane (replaces scattered
//    per-hit stores + zero-pad loop).
//
// Replay-safe: g_tick monotone; parity zeroing re-establishes the counter
// invariant each call. Deterministic: hits ranked by unique original index.
//
// Hit predicate bit-identical to verified formula (rel_err 0.0 x10):
//   s = ((x*x + y*y) + z*z)  (mul/add, no fma contraction)
//   dot = fmaf(z1,z2, fmaf(y1,y2, x1*x2))
//   d2  = (s1 + s2) - 2*dot;  hit iff d2 <= r^2

#define BQ_N1 4096
#define BQ_N2 16384
#define BQ_K 32
#define BQ_R2 0.0064f
#define BQ_R2P 0.00641f
#define BQ_G 12
#define BQ_NC (BQ_G * BQ_G * BQ_G)  // 1728
#define BQ_CAP 48
#define BQ_BUF 128
#define NBLK 256
#define NTHR 512
#define NWARP 16
#define ZPB 7                       // 256*7 = 1792 >= 1728
#define PPB 64                      // 256*64 = 16384

__device__ unsigned g_tick;             // entry tickets (monotone)
__device__ unsigned g_arrive;           // barrier arrival tickets (monotone)
__device__ unsigned g_release;          // barrier release generations
__device__ int g_n[2][BQ_NC];           // parity-double-buffered counts
__device__ float4 g_cp[BQ_NC * BQ_CAP]; // x, y, z, idx_bits

__device__ __forceinline__ int cell1(float v) {
    int c = (int)(v * (float)BQ_G);
    return c < 0 ? 0 : (c > BQ_G - 1 ? BQ_G - 1 : c);
}

// Fence-free grid barrier (acq_rel ticket / release-word split).
// 256 blocks co-resident (launch_bounds(512,2): 296 >= 256) -> deadlock-free.
__device__ __forceinline__ void gbar() {
    __syncthreads();
    if (threadIdx.x == 0) {
        unsigned my;
        asm volatile("atom.add.acq_rel.gpu.global.u32 %0, [%1], %2;"
                     : "=r"(my) : "l"(&g_arrive), "r"(1u) : "memory");
        unsigned target = my / NBLK + 1u;
        if (my % NBLK == NBLK - 1u) {
            asm volatile("red.add.release.gpu.global.u32 [%0], %1;"
                         :: "l"(&g_release), "r"(1u) : "memory");
        } else {
            unsigned v;
            do {
                __nanosleep(20);
                asm volatile("ld.acquire.gpu.global.u32 %0, [%1];"
                             : "=r"(v) : "l"(&g_release) : "memory");
            } while (v < target);
        }
    }
    __syncthreads();
}

__global__ __launch_bounds__(NTHR, 2) void bq_all(const float* __restrict__ p1,
                                                  const float* __restrict__ p2,
                                                  float* __restrict__ out) {
    __shared__ int sh_key[NWARP][BQ_BUF];    // 8 KB packed hit records
    __shared__ float sh_out[NWARP][BQ_K * 4];// 8 KB staged outputs
    __shared__ int s_wcnt[NWARP];
    __shared__ unsigned s_call;

    int tid = threadIdx.x;
    int warp = tid >> 5;
    int lane = tid & 31;
    int q = blockIdx.x * NWARP + warp;       // 4096 queries, one per warp

    // ---- Entry: non-blocking call-index ticket ----
    if (tid == 0) s_call = atomicAdd(&g_tick, 1u) / NBLK;
    if (tid < NWARP) s_wcnt[tid] = 0;
    __syncthreads();
    int par = (int)(s_call & 1u);
    int* cnts = g_n[par];

    // Zero the OTHER parity buffer for the next call (no reader exists).
    if (tid < ZPB) {
        int c = blockIdx.x * ZPB + tid;
        if (c < BQ_NC) g_n[1 - par][c] = 0;
    }

    // ---- Build: 64 points/block into g_n[par]/g_cp ----
    if (tid < PPB) {
        int j = blockIdx.x * PPB + tid;
        float px = p2[3 * j + 0];
        float py = p2[3 * j + 1];
        float pz = p2[3 * j + 2];
        int c = (cell1(pz) * BQ_G + cell1(py)) * BQ_G + cell1(px);
        int slot = atomicAdd(&cnts[c], 1);
        if (slot < BQ_CAP)
            g_cp[c * BQ_CAP + slot] =
                make_float4(px, py, pz, __int_as_float(j));
    }

    // Query-point setup (overlaps build latency).
    float x1 = p1[3 * q + 0];
    float y1 = p1[3 * q + 1];
    float z1 = p1[3 * q + 2];
    float s1 = __fadd_rn(__fadd_rn(__fmul_rn(x1, x1), __fmul_rn(y1, y1)),
                         __fmul_rn(z1, z1));
    int cx = cell1(x1), cy = cell1(y1), cz = cell1(z1);
    int xlo = cx > 0 ? cx - 1 : 0;
    int xhi = cx < BQ_G - 1 ? cx + 1 : BQ_G - 1;
    const float invG = 1.0f / (float)BQ_G;
    float dxl = x1 - (float)cx * invG, dxr = (float)(cx + 1) * invG - x1;
    float dyl = y1 - (float)cy * invG, dyr = (float)(cy + 1) * invG - y1;
    float dzl = z1 - (float)cz * invG, dzr = (float)(cz + 1) * invG - z1;
    float dxl2 = dxl * dxl, dxr2 = dxr * dxr;

    gbar();  // the only barrier: build complete -> query may read

    // ---- Query ----
    int* keyb = sh_key[warp];
    int* wcnt = &s_wcnt[warp];

    // Row descriptors: all 27 counter loads issue as one independent wave.
    int rbase[9], rpack[9];  // rpack = n0 | n01<<8 | tot<<16
    #pragma unroll
    for (int r = 0; r < 9; r++) {
        int dzi = r / 3 - 1, dyi = r % 3 - 1;
        int zz = cz + dzi, yy = cy + dyi;
        float ddz = (dzi < 0) ? dzl : ((dzi > 0) ? dzr : 0.0f);
        float ddy = (dyi < 0) ? dyl : ((dyi > 0) ? dyr : 0.0f);
        float dyz2 = ddz * ddz + ddy * ddy;
        bool ok = (zz >= 0) && (zz < BQ_G) && (yy >= 0) && (yy < BQ_G) &&
                  (dyz2 <= BQ_R2P);
        int xl = xlo, xh = xhi;
        if (xl < cx && dxl2 + dyz2 > BQ_R2P) xl = cx;
        if (xh > cx && dxr2 + dyz2 > BQ_R2P) xh = cx;
        int c0 = (zz * BQ_G + yy) * BQ_G + xl;
        int nc = xh - xl + 1;
        int n0 = 0, n1 = 0, n2 = 0;
        if (ok) {
            n0 = min(cnts[c0], BQ_CAP);
            if (nc > 1) n1 = min(cnts[c0 + 1], BQ_CAP);
            if (nc > 2) n2 = min(cnts[c0 + 2], BQ_CAP);
        }
        rbase[r] = c0 * BQ_CAP;
        rpack[r] = n0 | ((n0 + n1) << 8) | ((n0 + n1 + n2) << 16);
    }

    // Rows in 3 groups of 3: each group's candidate loads issue back-to-back.
    #pragma unroll
    for (int grp = 0; grp < 3; grp++) {
        float4 pb[3];
        int ta[3], tt[3];
        #pragma unroll
        for (int k = 0; k < 3; k++) {
            int r = grp * 3 + k;
            int n0 = rpack[r] & 0xff;
            int n01 = (rpack[r] >> 8) & 0xff;
            int tot = rpack[r] >> 16;
            tt[k] = tot;
            int t = lane;
            int a = rbase[r] + (t < n0 ? t
                    : (t < n01 ? BQ_CAP + t - n0 : 2 * BQ_CAP + t - n01));
            ta[k] = a;
            if (t < tot) pb[k] = g_cp[a];
        }
        #pragma unroll
        for (int k = 0; k < 3; k++) {
            if (lane < tt[k]) {
                float4 p = pb[k];
                float s2 = __fadd_rn(
                    __fadd_rn(__fmul_rn(p.x, p.x), __fmul_rn(p.y, p.y)),
                    __fmul_rn(p.z, p.z));
                float dot = fmaf(z1, p.z, fmaf(y1, p.y, __fmul_rn(x1, p.x)));
                float d2 = __fsub_rn(__fadd_rn(s1, s2), __fmul_rn(2.0f, dot));
                if (d2 <= BQ_R2) {
                    int pos = atomicAdd(wcnt, 1);
                    if (pos < BQ_BUF)
                        keyb[pos] = (__float_as_int(p.w) << 17) | ta[k];
                }
            }
        }
        // Overflow pass: rows with tot > 32 (uncommon).
        #pragma unroll
        for (int k = 0; k < 3; k++) {
            int r = grp * 3 + k;
            int n0 = rpack[r] & 0xff;
            int n01 = (rpack[r] >> 8) & 0xff;
            for (int t = 32 + lane; t < tt[k]; t += 32) {
                int a = rbase[r] + (t < n0 ? t
                        : (t < n01 ? BQ_CAP + t - n0 : 2 * BQ_CAP + t - n01));
                float4 p = g_cp[a];
                float s2 = __fadd_rn(
                    __fadd_rn(__fmul_rn(p.x, p.x), __fmul_rn(p.y, p.y)),
                    __fmul_rn(p.z, p.z));
                float dot = fmaf(z1, p.z, fmaf(y1, p.y, __fmul_rn(x1, p.x)));
                float d2 = __fsub_rn(__fadd_rn(s1, s2), __fmul_rn(2.0f, dot));
                if (d2 <= BQ_R2) {
                    int pos = atomicAdd(wcnt, 1);
                    if (pos < BQ_BUF)
                        keyb[pos] = (__float_as_int(p.w) << 17) | a;
                }
            }
        }
    }
    __syncwarp();
    int cnt = *wcnt;

    // ---- Staged epilogue ----
    float* ob = sh_out[warp];  // [0..31] mapping, [32..127] coords (rank-major)
    ob[lane] = 0.0f;
    ob[32 + lane] = 0.0f;
    ob[64 + lane] = 0.0f;
    ob[96 + lane] = 0.0f;
    __syncwarp();

    int cc = cnt < BQ_BUF ? cnt : BQ_BUF;
    // Rank by packed key (idx-major, idx unique) -> reference's "first K in
    // ascending original index" order, independent of append order.
    for (int e0 = lane; e0 < cc; e0 += 32) {
        int key = keyb[e0];
        int rank = 0;
        for (int i = 0; i < cc; i++) rank += (keyb[i] < key);
        if (rank < BQ_K) {
            float4 p = g_cp[key & 0x1FFFF];  // L1-hot reload
            ob[rank] = (float)(key >> 17);
            ob[32 + rank * 3 + 0] = p.x;
            ob[32 + rank * 3 + 1] = p.y;
            ob[32 + rank * 3 + 2] = p.z;
        }
    }
    __syncwarp();

    float* mapping = out + (size_t)q * BQ_K;
    float* coords  = out + (size_t)BQ_N1 * BQ_K + BQ_N1 + (size_t)q * BQ_K * 3;
    mapping[lane] = ob[lane];
    coords[lane] = ob[32 + lane];
    coords[32 + lane] = ob[64 + lane];
    coords[64 + lane] = ob[96 + lane];
    if (lane == 0)
        out[(size_t)BQ_N1 * BQ_K + q] = (float)(cnt < BQ_K ? cnt : BQ_K);
}

extern "C" void kernel_launch(void* const* d_in, const int* in_sizes, int n_in,
                              void* d_out, int out_size) {
    const float* p1 = (const float*)d_in[0];
    const float* p2 = (const float*)d_in[1];
    float* out = (float*)d_out;
    bq_all<<<NBLK, NTHR>>>(p1, p2, out);
}